// round 2
// baseline (speedup 1.0000x reference)
#include <cuda_runtime.h>
#include <math.h>

#define BATCH 16384
#define FEAT  2048
#define F4    (FEAT / 4)          // 512 float4 per row
#define WARPS_PER_BLOCK 8
#define THREADS (WARPS_PER_BLOCK * 32)
#define GRID (BATCH / WARPS_PER_BLOCK)   // 2048 blocks

__global__ void zero_out_kernel(float* out) {
    out[0] = 0.0f;
}

__global__ __launch_bounds__(THREADS)
void triplet_loss_kernel(const float4* __restrict__ anchor,
                         const float4* __restrict__ positive,
                         const float4* __restrict__ negative,
                         float* __restrict__ out) {
    const int lane = threadIdx.x & 31;
    const int warp_in_block = threadIdx.x >> 5;
    const int row = blockIdx.x * WARPS_PER_BLOCK + warp_in_block;

    const float4* __restrict__ ar = anchor   + (size_t)row * F4;
    const float4* __restrict__ pr = positive + (size_t)row * F4;
    const float4* __restrict__ nr = negative + (size_t)row * F4;

    float dp = 0.0f;  // sum (a-p)^2
    float dn = 0.0f;  // sum (a-n)^2

    // 512 float4 per row, 32 lanes -> 16 iterations per lane per array.
    #pragma unroll 16
    for (int i = lane; i < F4; i += 32) {
        float4 av = ar[i];
        float4 pv = pr[i];
        float4 nv = nr[i];

        float d;
        d = av.x - pv.x; dp = fmaf(d, d, dp);
        d = av.y - pv.y; dp = fmaf(d, d, dp);
        d = av.z - pv.z; dp = fmaf(d, d, dp);
        d = av.w - pv.w; dp = fmaf(d, d, dp);

        d = av.x - nv.x; dn = fmaf(d, d, dn);
        d = av.y - nv.y; dn = fmaf(d, d, dn);
        d = av.z - nv.z; dn = fmaf(d, d, dn);
        d = av.w - nv.w; dn = fmaf(d, d, dn);
    }

    // Warp reduction
    #pragma unroll
    for (int off = 16; off > 0; off >>= 1) {
        dp += __shfl_xor_sync(0xFFFFFFFFu, dp, off);
        dn += __shfl_xor_sync(0xFFFFFFFFu, dn, off);
    }

    __shared__ float partial[WARPS_PER_BLOCK];
    if (lane == 0) {
        float loss = sqrtf(dp) - sqrtf(dn) + 1.0f;      // MARGIN = 1.0
        loss = fmaxf(loss, 0.0f) * (1.0f / (float)BATCH);
        partial[warp_in_block] = loss;
    }
    __syncthreads();

    // One atomic per block
    if (threadIdx.x == 0) {
        float acc = 0.0f;
        #pragma unroll
        for (int w = 0; w < WARPS_PER_BLOCK; w++) acc += partial[w];
        atomicAdd(out, acc);
    }
}

extern "C" void kernel_launch(void* const* d_in, const int* in_sizes, int n_in,
                              void* d_out, int out_size) {
    const float4* anchor   = (const float4*)d_in[0];
    const float4* positive = (const float4*)d_in[1];
    const float4* negative = (const float4*)d_in[2];
    float* out = (float*)d_out;

    zero_out_kernel<<<1, 1>>>(out);
    triplet_loss_kernel<<<GRID, THREADS>>>(anchor, positive, negative, out);
}

// round 3
// speedup vs baseline: 1.0438x; 1.0438x over previous
#include <cuda_runtime.h>
#include <math.h>

#define BATCH 16384
#define FEAT  2048
#define F4    (FEAT / 4)          // 512 float4 per row
#define WARPS_PER_BLOCK 8
#define THREADS (WARPS_PER_BLOCK * 32)
#define GRID 1024                 // single wave: 1024 <= 148 SMs * 7 blocks
#define TOTAL_WARPS (GRID * WARPS_PER_BLOCK)   // 8192
#define ROWS_PER_WARP (BATCH / TOTAL_WARPS)    // 2

__global__ void zero_out_kernel(float* out) {
    out[0] = 0.0f;
}

__device__ __forceinline__ float4 ldcs4(const float4* p) {
    return __ldcs(p);   // streaming (evict-first) — data is read exactly once
}

__global__ __launch_bounds__(THREADS, 7)
void triplet_loss_kernel(const float4* __restrict__ anchor,
                         const float4* __restrict__ positive,
                         const float4* __restrict__ negative,
                         float* __restrict__ out) {
    const int lane = threadIdx.x & 31;
    const int warp_in_block = threadIdx.x >> 5;
    const int gwarp = blockIdx.x * WARPS_PER_BLOCK + warp_in_block;  // 0..8191

    float block_acc = 0.0f;  // only meaningful on lane 0

    #pragma unroll
    for (int r = 0; r < ROWS_PER_WARP; r++) {
        const int row = gwarp + r * TOTAL_WARPS;   // w and w + 8192

        const float4* __restrict__ ar = anchor   + (size_t)row * F4;
        const float4* __restrict__ pr = positive + (size_t)row * F4;
        const float4* __restrict__ nr = negative + (size_t)row * F4;

        float dp = 0.0f;  // sum (a-p)^2
        float dn = 0.0f;  // sum (a-n)^2

        // 512 float4 per row, 32 lanes -> 16 iterations per lane.
        #pragma unroll 16
        for (int i = lane; i < F4; i += 32) {
            float4 av = ldcs4(ar + i);
            float4 pv = ldcs4(pr + i);
            float4 nv = ldcs4(nr + i);

            float d;
            d = av.x - pv.x; dp = fmaf(d, d, dp);
            d = av.y - pv.y; dp = fmaf(d, d, dp);
            d = av.z - pv.z; dp = fmaf(d, d, dp);
            d = av.w - pv.w; dp = fmaf(d, d, dp);

            d = av.x - nv.x; dn = fmaf(d, d, dn);
            d = av.y - nv.y; dn = fmaf(d, d, dn);
            d = av.z - nv.z; dn = fmaf(d, d, dn);
            d = av.w - nv.w; dn = fmaf(d, d, dn);
        }

        // Warp reduction
        #pragma unroll
        for (int off = 16; off > 0; off >>= 1) {
            dp += __shfl_xor_sync(0xFFFFFFFFu, dp, off);
            dn += __shfl_xor_sync(0xFFFFFFFFu, dn, off);
        }

        if (lane == 0) {
            float loss = sqrtf(dp) - sqrtf(dn) + 1.0f;      // MARGIN = 1.0
            block_acc += fmaxf(loss, 0.0f) * (1.0f / (float)BATCH);
        }
    }

    __shared__ float partial[WARPS_PER_BLOCK];
    if (lane == 0) partial[warp_in_block] = block_acc;
    __syncthreads();

    // One atomic per block (1024 total)
    if (threadIdx.x == 0) {
        float acc = 0.0f;
        #pragma unroll
        for (int w = 0; w < WARPS_PER_BLOCK; w++) acc += partial[w];
        atomicAdd(out, acc);
    }
}

extern "C" void kernel_launch(void* const* d_in, const int* in_sizes, int n_in,
                              void* d_out, int out_size) {
    const float4* anchor   = (const float4*)d_in[0];
    const float4* positive = (const float4*)d_in[1];
    const float4* negative = (const float4*)d_in[2];
    float* out = (float*)d_out;

    zero_out_kernel<<<1, 1>>>(out);
    triplet_loss_kernel<<<GRID, THREADS>>>(anchor, positive, negative, out);
}